// round 15
// baseline (speedup 1.0000x reference)
#include <cuda_runtime.h>
#include <cuda_fp16.h>
#include <cstdint>

#define N_USER  100000
#define N_PHOTO 200000
#define K_IN    256
#define N_OUT   64
#define E_MAX   1048576

typedef unsigned long long ull;

// Scratch (static device globals; no allocs). Wh tables fp16.
__device__ __half g_Wh_user [(size_t)N_USER  * N_OUT];  // 12.8 MB
__device__ __half g_Wh_photo[(size_t)N_PHOTO * N_OUT];  // 25.6 MB
__device__ ull    g_Bpack_likes  [8192];                // packed tf32 W (64 KB)
__device__ ull    g_Bpack_likedby[8192];
// CSR scratch (per dst ntype)
__device__ int g_degi_user  [N_USER];
__device__ int g_degi_photo [N_PHOTO];
__device__ int g_starts_user [N_USER];
__device__ int g_starts_photo[N_PHOTO];
__device__ int g_cursor_user [N_USER];
__device__ int g_cursor_photo[N_PHOTO];
__device__ int g_eidx_likes  [E_MAX];   // src ids grouped by photo dst
__device__ int g_eidx_likedby[E_MAX];   // src ids grouped by user dst
__device__ int g_bsum_a[256], g_boff_a[256];
__device__ int g_bsum_b[256], g_boff_b[256];

__device__ __forceinline__ unsigned f2tf32(float f) {
    unsigned r;
    asm("cvt.rna.tf32.f32 %0, %1;" : "=r"(r) : "f"(f));
    return r;
}

__device__ __forceinline__ void cp_async16(unsigned dst_smem, const void* src,
                                           unsigned src_bytes) {
    asm volatile("cp.async.cg.shared.global [%0], [%1], 16, %2;"
                 :: "r"(dst_smem), "l"(src), "r"(src_bytes) : "memory");
}

// ---------------------------------------------------------------------------
// Prepack W[256,64] -> fragment-ordered tf32 ull table (see R5 comment).
// ---------------------------------------------------------------------------
__global__ __launch_bounds__(256) void prepack_B(
    const float* __restrict__ W, ull* __restrict__ out)
{
    int i = blockIdx.x * 256 + threadIdx.x;      // 0..8191
    int e = i & 1, u = i >> 1;
    int t = u & 3, g = (u >> 2) & 7, jj = (u >> 5) & 3, kk = u >> 7;
    int n  = (2 * jj + e) * 8 + g;
    int k1 = kk * 8 + t;
    unsigned lo = f2tf32(W[(size_t)k1 * 64 + n]);
    unsigned hi = f2tf32(W[(size_t)(k1 + 4) * 64 + n]);
    out[i] = ((ull)hi << 32) | (ull)lo;
}

// ---------------------------------------------------------------------------
// Tensor-core GEMM (R13 proven config): BM=256, STAGES=2, 2 CTAs/SM.
// ---------------------------------------------------------------------------
#define BM        256
#define STAGES    2
#define ASTRIDE   36
#define AS_STAGE  (BM * ASTRIDE)               // 9216 floats = 36 KB
#define BS_STAGE  1024                         // ulls = 8 KB
#define SMEM_A_BYTES (STAGES * AS_STAGE * 4)   // 73728
#define SMEM_B_BYTES (STAGES * BS_STAGE * 8)   // 16384
#define GEMM_SMEM    (SMEM_A_BYTES + SMEM_B_BYTES)   // 90112

__global__ __launch_bounds__(256, 2) void gemm_tc(
    const float* __restrict__ A, const ull* __restrict__ Bpack,
    const float* __restrict__ bias, __half* __restrict__ C, int M)
{
    extern __shared__ char smem_raw[];
    float* As = (float*)smem_raw;
    ull*   Bs = (ull*)(smem_raw + SMEM_A_BYTES);
    const unsigned sA = (unsigned)__cvta_generic_to_shared(As);
    const unsigned sB = (unsigned)__cvta_generic_to_shared(Bs);

    const int tid  = threadIdx.x;
    const int lane = tid & 31;
    const int warp = tid >> 5;
    const int g = lane >> 2;
    const int t = lane & 3;
    const int rowBase = blockIdx.x * BM;
    const int segA = lane & 7;
    const int rA   = lane >> 3;

    float acc[2][8][4];
#pragma unroll
    for (int m = 0; m < 2; m++)
#pragma unroll
        for (int j = 0; j < 8; j++)
#pragma unroll
            for (int q = 0; q < 4; q++) acc[m][j][q] = 0.f;

#define ISSUE_CHUNK(c, stage)                                                  \
    do {                                                                       \
        _Pragma("unroll")                                                      \
        for (int it = 0; it < 8; it++) {                                       \
            int rin  = warp * 32 + it * 4 + rA;                                \
            int grow = rowBase + rin;                                          \
            const float* srcp = A + (size_t)grow * K_IN + (c) * 32 + segA * 4; \
            unsigned sz  = (grow < M) ? 16u : 0u;                              \
            unsigned dst = sA + ((stage) * AS_STAGE + rin * ASTRIDE            \
                                 + segA * 4) * 4;                              \
            cp_async16(dst, srcp, sz);                                         \
        }                                                                      \
        _Pragma("unroll")                                                      \
        for (int j = 0; j < 2; j++) {                                          \
            int chunk = tid + j * 256;                                         \
            const ull* srcb = Bpack + (size_t)(c) * 1024 + chunk * 2;          \
            unsigned dst = sB + ((stage) * BS_STAGE + chunk * 2) * 8;          \
            cp_async16(dst, srcb, 16u);                                        \
        }                                                                      \
    } while (0)

    // prologue: both stages
    ISSUE_CHUNK(0, 0);
    asm volatile("cp.async.commit_group;" ::: "memory");
    ISSUE_CHUNK(1, 1);
    asm volatile("cp.async.commit_group;" ::: "memory");

    for (int c = 0; c < 8; c++) {
        asm volatile("cp.async.wait_group 1;" ::: "memory");
        __syncthreads();                          // chunk c visible CTA-wide

        const int s = c & 1;
        const float* as = As + s * AS_STAGE + (warp * 32) * ASTRIDE;
        const uint4* bs = (const uint4*)(Bs + s * BS_STAGE);
#pragma unroll
        for (int kl = 0; kl < 4; kl++) {
            uint4 bv[4];
#pragma unroll
            for (int jj = 0; jj < 4; jj++)
                bv[jj] = bs[kl * 128 + jj * 32 + g * 4 + t];   // conflict-free
#pragma unroll
            for (int m = 0; m < 2; m++) {
                const float* am = as + m * 16 * ASTRIDE;
                unsigned a0 = f2tf32(am[(g)     * ASTRIDE + kl * 8 + t]);
                unsigned a1 = f2tf32(am[(g + 8) * ASTRIDE + kl * 8 + t]);
                unsigned a2 = f2tf32(am[(g)     * ASTRIDE + kl * 8 + t + 4]);
                unsigned a3 = f2tf32(am[(g + 8) * ASTRIDE + kl * 8 + t + 4]);
#pragma unroll
                for (int jj = 0; jj < 4; jj++) {
                    asm volatile(
                        "mma.sync.aligned.m16n8k8.row.col.f32.tf32.tf32.f32 "
                        "{%0,%1,%2,%3}, {%4,%5,%6,%7}, {%8,%9}, {%0,%1,%2,%3};"
                        : "+f"(acc[m][2 * jj][0]), "+f"(acc[m][2 * jj][1]),
                          "+f"(acc[m][2 * jj][2]), "+f"(acc[m][2 * jj][3])
                        : "r"(a0), "r"(a1), "r"(a2), "r"(a3),
                          "r"(bv[jj].x), "r"(bv[jj].y));
                    asm volatile(
                        "mma.sync.aligned.m16n8k8.row.col.f32.tf32.tf32.f32 "
                        "{%0,%1,%2,%3}, {%4,%5,%6,%7}, {%8,%9}, {%0,%1,%2,%3};"
                        : "+f"(acc[m][2 * jj + 1][0]), "+f"(acc[m][2 * jj + 1][1]),
                          "+f"(acc[m][2 * jj + 1][2]), "+f"(acc[m][2 * jj + 1][3])
                        : "r"(a0), "r"(a1), "r"(a2), "r"(a3),
                          "r"(bv[jj].z), "r"(bv[jj].w));
                }
            }
        }

        // refill the stage just consumed (all threads past compute of c)
        __syncthreads();
        if (c + 2 < 8) ISSUE_CHUNK(c + 2, s);
        asm volatile("cp.async.commit_group;" ::: "memory");
    }

    // epilogue: bias + fp16 store
#pragma unroll
    for (int m = 0; m < 2; m++) {
        int r0 = rowBase + warp * 32 + m * 16 + g;
#pragma unroll
        for (int j = 0; j < 8; j++) {
            int col = j * 8 + 2 * t;
            float b0 = __ldg(&bias[col]), b1 = __ldg(&bias[col + 1]);
            if (r0 < M)
                *(__half2*)&C[(size_t)r0 * N_OUT + col] =
                    __floats2half2_rn(acc[m][j][0] + b0, acc[m][j][1] + b1);
            if (r0 + 8 < M)
                *(__half2*)&C[(size_t)(r0 + 8) * N_OUT + col] =
                    __floats2half2_rn(acc[m][j][2] + b0, acc[m][j][3] + b1);
        }
    }
#undef ISSUE_CHUNK
}

// ---------------------------------------------------------------------------
// CSR build: int in-degrees -> exclusive prefix scan -> cursor fill.
// ---------------------------------------------------------------------------
__global__ __launch_bounds__(256) void degree_int_kernel(
    const int* __restrict__ dst, int* __restrict__ deg, int E)
{
    int base = (blockIdx.x * 256 + threadIdx.x) * 4;
    if (base + 3 < E) {
        int4 d = *(const int4*)(dst + base);
        atomicAdd(&deg[d.x], 1);
        atomicAdd(&deg[d.y], 1);
        atomicAdd(&deg[d.z], 1);
        atomicAdd(&deg[d.w], 1);
    } else {
        for (int e = base; e < E; e++) atomicAdd(&deg[dst[e]], 1);
    }
}

#define SCAN_BLK 1024   // elements per scan block (256 thr x 4)

__global__ __launch_bounds__(256) void scan_partial(
    const int* __restrict__ deg, int n, int* __restrict__ bsum)
{
    __shared__ int sh[256];
    int b = blockIdx.x, tid = threadIdx.x;
    int base = b * SCAN_BLK;
    int s = 0;
#pragma unroll
    for (int j = 0; j < 4; j++) {
        int idx = base + tid * 4 + j;
        s += (idx < n) ? deg[idx] : 0;
    }
    sh[tid] = s;
    __syncthreads();
    for (int o = 128; o > 0; o >>= 1) {
        if (tid < o) sh[tid] += sh[tid + o];
        __syncthreads();
    }
    if (tid == 0) bsum[b] = sh[0];
}

__global__ __launch_bounds__(256) void scan_bsums(
    const int* __restrict__ bsum, int nb, int* __restrict__ boff)
{
    __shared__ int sh[256];
    int tid = threadIdx.x;
    int v = (tid < nb) ? bsum[tid] : 0;
    sh[tid] = v;
    __syncthreads();
    for (int o = 1; o < 256; o <<= 1) {
        int y = (tid >= o) ? sh[tid - o] : 0;
        __syncthreads();
        sh[tid] += y;
        __syncthreads();
    }
    if (tid < nb) boff[tid] = sh[tid] - v;   // exclusive
}

__global__ __launch_bounds__(256) void scan_final(
    const int* __restrict__ deg, int n, const int* __restrict__ boff,
    int* __restrict__ starts, int* __restrict__ cursor)
{
    __shared__ int sh[256];
    int b = blockIdx.x, tid = threadIdx.x;
    int base = b * SCAN_BLK + tid * 4;
    int v[4];
#pragma unroll
    for (int j = 0; j < 4; j++) v[j] = (base + j < n) ? deg[base + j] : 0;
    int tsum = v[0] + v[1] + v[2] + v[3];
    sh[tid] = tsum;
    __syncthreads();
    for (int o = 1; o < 256; o <<= 1) {
        int y = (tid >= o) ? sh[tid - o] : 0;
        __syncthreads();
        sh[tid] += y;
        __syncthreads();
    }
    int off = boff[b] + sh[tid] - tsum;   // block base + thread-exclusive
    int e = 0;
#pragma unroll
    for (int j = 0; j < 4; j++) {
        if (base + j < n) {
            starts[base + j] = off + e;
            cursor[base + j] = off + e;
        }
        e += v[j];
    }
}

__global__ __launch_bounds__(256) void fill_csr(
    const int* __restrict__ src, const int* __restrict__ dst,
    int* __restrict__ cursor, int* __restrict__ eidx, int E)
{
    int base = (blockIdx.x * 256 + threadIdx.x) * 4;
    if (base + 3 < E) {
        int4 s = *(const int4*)(src + base);
        int4 d = *(const int4*)(dst + base);
        int p0 = atomicAdd(&cursor[d.x], 1); eidx[p0] = s.x;
        int p1 = atomicAdd(&cursor[d.y], 1); eidx[p1] = s.y;
        int p2 = atomicAdd(&cursor[d.z], 1); eidx[p2] = s.z;
        int p3 = atomicAdd(&cursor[d.w], 1); eidx[p3] = s.w;
    } else {
        for (int e = base; e < E; e++) {
            int p = atomicAdd(&cursor[dst[e]], 1);
            eidx[p] = src[e];
        }
    }
}

// ---------------------------------------------------------------------------
// CSR gather-aggregate over fp16 Wh, SOFTWARE-PIPELINED:
// 16 threads/node, lane loads 8B per edge. Double-buffered batches: while
// batch A's Wh loads are being accumulated (waited on), batch B's eidx AND
// Wh loads are already in flight -> hides one full L2 round-trip per batch.
// ---------------------------------------------------------------------------
__device__ __forceinline__ float4 half4_to_float4(uint2 u) {
    __half2 h0 = *(__half2*)&u.x;
    __half2 h1 = *(__half2*)&u.y;
    float2 f0 = __half22float2(h0);
    float2 f1 = __half22float2(h1);
    return make_float4(f0.x, f0.y, f1.x, f1.y);
}

__global__ __launch_bounds__(256) void gather_mean_kernel(
    const __half* __restrict__ Wh, const int* __restrict__ starts,
    const int* __restrict__ deg, const int* __restrict__ eidx,
    float* __restrict__ out, int n)
{
    int t = blockIdx.x * 256 + threadIdx.x;
    int node = t >> 4;
    if (node >= n) return;
    int lane = t & 15;

    int st = __ldg(&starts[node]);
    int dg = __ldg(&deg[node]);
    int end = st + dg;
    const int nb = dg >> 2;            // full 4-edge batches

    float4 a0 = make_float4(0.f, 0.f, 0.f, 0.f), a1 = a0, a2 = a0, a3 = a0;

    uint2 uA[4], uB[4];
    int k = st;

    // prologue: issue batch 0 into A
    if (nb > 0) {
#pragma unroll
        for (int i = 0; i < 4; i++) {
            int s = __ldg(&eidx[k + i]);
            uA[i] = __ldg(((const uint2*)(Wh + (size_t)s * N_OUT)) + lane);
        }
        k += 4;
    }

    bool useA = true;
    for (int b = 0; b < nb; b++) {
        bool more = (b + 1 < nb);
        if (useA) {
            if (more) {
#pragma unroll
                for (int i = 0; i < 4; i++) {
                    int s = __ldg(&eidx[k + i]);
                    uB[i] = __ldg(((const uint2*)(Wh + (size_t)s * N_OUT)) + lane);
                }
                k += 4;
            }
            float4 v0 = half4_to_float4(uA[0]);
            float4 v1 = half4_to_float4(uA[1]);
            float4 v2 = half4_to_float4(uA[2]);
            float4 v3 = half4_to_float4(uA[3]);
            a0.x += v0.x; a0.y += v0.y; a0.z += v0.z; a0.w += v0.w;
            a1.x += v1.x; a1.y += v1.y; a1.z += v1.z; a1.w += v1.w;
            a2.x += v2.x; a2.y += v2.y; a2.z += v2.z; a2.w += v2.w;
            a3.x += v3.x; a3.y += v3.y; a3.z += v3.z; a3.w += v3.w;
        } else {
            if (more) {
#pragma unroll
                for (int i = 0; i < 4; i++) {
                    int s = __ldg(&eidx[k + i]);
                    uA[i] = __ldg(((const uint2*)(Wh + (size_t)s * N_OUT)) + lane);
                }
                k += 4;
            }
            float4 v0 = half4_to_float4(uB[0]);
            float4 v1 = half4_to_float4(uB[1]);
            float4 v2 = half4_to_float4(uB[2]);
            float4 v3 = half4_to_float4(uB[3]);
            a0.x += v0.x; a0.y += v0.y; a0.z += v0.z; a0.w += v0.w;
            a1.x += v1.x; a1.y += v1.y; a1.z += v1.z; a1.w += v1.w;
            a2.x += v2.x; a2.y += v2.y; a2.z += v2.z; a2.w += v2.w;
            a3.x += v3.x; a3.y += v3.y; a3.z += v3.z; a3.w += v3.w;
        }
        useA = !useA;
    }

    // tail: remaining 0-3 edges
    for (int kk = st + nb * 4; kk < end; kk++) {
        int s = __ldg(&eidx[kk]);
        uint2 u = __ldg(((const uint2*)(Wh + (size_t)s * N_OUT)) + lane);
        float4 v = half4_to_float4(u);
        a0.x += v.x; a0.y += v.y; a0.z += v.z; a0.w += v.w;
    }

    float4 acc = make_float4(a0.x + a1.x + a2.x + a3.x,
                             a0.y + a1.y + a2.y + a3.y,
                             a0.z + a1.z + a2.z + a3.z,
                             a0.w + a1.w + a2.w + a3.w);
    float inv = 1.0f / (float)max(dg, 1);
    acc.x *= inv; acc.y *= inv; acc.z *= inv; acc.w *= inv;
    ((float4*)(out + (size_t)node * N_OUT))[lane] = acc;
}

// ---------------------------------------------------------------------------
extern "C" void kernel_launch(void* const* d_in, const int* in_sizes, int n_in,
                              void* d_out, int out_size)
{
    const float* user_feats  = (const float*)d_in[0];
    const float* photo_feats = (const float*)d_in[1];
    const float* W_likes     = (const float*)d_in[2];
    const float* b_likes     = (const float*)d_in[3];
    const float* W_likedby   = (const float*)d_in[4];
    const float* b_likedby   = (const float*)d_in[5];
    const int*   likes_src   = (const int*)d_in[6];
    const int*   likes_dst   = (const int*)d_in[7];
    const int*   likedby_src = (const int*)d_in[8];
    const int*   likedby_dst = (const int*)d_in[9];
    const int E1 = in_sizes[6];
    const int E2 = in_sizes[8];

    float* out_user  = (float*)d_out;
    float* out_photo = (float*)d_out + (size_t)N_USER * N_OUT;

    __half *wh_user, *wh_photo;
    ull *bp_likes, *bp_likedby;
    int *degi_u, *degi_p, *st_u, *st_p, *cur_u, *cur_p, *eix_l, *eix_lb;
    int *bsum_a, *boff_a, *bsum_b, *boff_b;
    cudaGetSymbolAddress((void**)&wh_user,  g_Wh_user);
    cudaGetSymbolAddress((void**)&wh_photo, g_Wh_photo);
    cudaGetSymbolAddress((void**)&bp_likes,   g_Bpack_likes);
    cudaGetSymbolAddress((void**)&bp_likedby, g_Bpack_likedby);
    cudaGetSymbolAddress((void**)&degi_u, g_degi_user);
    cudaGetSymbolAddress((void**)&degi_p, g_degi_photo);
    cudaGetSymbolAddress((void**)&st_u,   g_starts_user);
    cudaGetSymbolAddress((void**)&st_p,   g_starts_photo);
    cudaGetSymbolAddress((void**)&cur_u,  g_cursor_user);
    cudaGetSymbolAddress((void**)&cur_p,  g_cursor_photo);
    cudaGetSymbolAddress((void**)&eix_l,  g_eidx_likes);
    cudaGetSymbolAddress((void**)&eix_lb, g_eidx_likedby);
    cudaGetSymbolAddress((void**)&bsum_a, g_bsum_a);
    cudaGetSymbolAddress((void**)&boff_a, g_boff_a);
    cudaGetSymbolAddress((void**)&bsum_b, g_bsum_b);
    cudaGetSymbolAddress((void**)&boff_b, g_boff_b);

    static cudaStream_t s_b = nullptr, s_aux = nullptr, s_c = nullptr;
    static cudaEvent_t evStart, evCSRp, evCSRu, evB;
    if (!s_b) {
        int loPri, hiPri;
        cudaDeviceGetStreamPriorityRange(&loPri, &hiPri);
        cudaStreamCreateWithPriority(&s_b,   cudaStreamNonBlocking, hiPri);
        cudaStreamCreateWithPriority(&s_aux, cudaStreamNonBlocking, loPri);
        cudaStreamCreateWithPriority(&s_c,   cudaStreamNonBlocking, loPri);
        cudaEventCreateWithFlags(&evStart, cudaEventDisableTiming);
        cudaEventCreateWithFlags(&evCSRp,  cudaEventDisableTiming);
        cudaEventCreateWithFlags(&evCSRu,  cudaEventDisableTiming);
        cudaEventCreateWithFlags(&evB,     cudaEventDisableTiming);
        cudaFuncSetAttribute(gemm_tc,
                             cudaFuncAttributeMaxDynamicSharedMemorySize,
                             GEMM_SMEM);
    }

    const int nbP = (N_PHOTO + SCAN_BLK - 1) / SCAN_BLK;   // 196
    const int nbU = (N_USER  + SCAN_BLK - 1) / SCAN_BLK;   // 98

    cudaEventRecord(evStart, 0);
    cudaStreamWaitEvent(s_b,   evStart, 0);
    cudaStreamWaitEvent(s_aux, evStart, 0);
    cudaStreamWaitEvent(s_c,   evStart, 0);

    // ---- Critical chain first: GEMMs claim the chip before CSR work. ----
    // MAIN: prepack(likedby) -> gemm_photo (the LONG gemm) -> gather_user.
    // s_b:  prepack(likes)   -> gemm_user  (the short gemm) -> gather_photo.
    prepack_B<<<32, 256>>>(W_likedby, bp_likedby);
    prepack_B<<<32, 256, 0, s_b>>>(W_likes, bp_likes);

    gemm_tc<<<(N_PHOTO + BM - 1) / BM, 256, GEMM_SMEM>>>(
        photo_feats, bp_likedby, b_likedby, wh_photo, N_PHOTO);
    gemm_tc<<<(N_USER + BM - 1) / BM, 256, GEMM_SMEM, s_b>>>(
        user_feats,  bp_likes,   b_likes,   wh_user,  N_USER);

    // ---- CSR builds (backfill the chip during the GEMM phase). ----
    // s_aux: CSR for 'likes' (grouped by photo dst).
    cudaMemsetAsync(degi_p, 0, N_PHOTO * sizeof(int), s_aux);
    degree_int_kernel<<<(E1 + 1023) / 1024, 256, 0, s_aux>>>(likes_dst, degi_p, E1);
    scan_partial<<<nbP, 256, 0, s_aux>>>(degi_p, N_PHOTO, bsum_a);
    scan_bsums<<<1, 256, 0, s_aux>>>(bsum_a, nbP, boff_a);
    scan_final<<<nbP, 256, 0, s_aux>>>(degi_p, N_PHOTO, boff_a, st_p, cur_p);
    fill_csr<<<(E1 + 1023) / 1024, 256, 0, s_aux>>>(likes_src, likes_dst, cur_p, eix_l, E1);
    cudaEventRecord(evCSRp, s_aux);

    // s_c: CSR for 'likedby' (grouped by user dst).
    cudaMemsetAsync(degi_u, 0, N_USER * sizeof(int), s_c);
    degree_int_kernel<<<(E2 + 1023) / 1024, 256, 0, s_c>>>(likedby_dst, degi_u, E2);
    scan_partial<<<nbU, 256, 0, s_c>>>(degi_u, N_USER, bsum_b);
    scan_bsums<<<1, 256, 0, s_c>>>(bsum_b, nbU, boff_b);
    scan_final<<<nbU, 256, 0, s_c>>>(degi_u, N_USER, boff_b, st_u, cur_u);
    fill_csr<<<(E2 + 1023) / 1024, 256, 0, s_c>>>(likedby_src, likedby_dst, cur_u, eix_lb, E2);
    cudaEventRecord(evCSRu, s_c);

    // ---- Gathers. ----
    // gather_photo: needs wh_user (s_b) + CSR_likes (s_aux) — overlaps both
    // gemm_photo's back half and gather_user.
    cudaStreamWaitEvent(s_b, evCSRp, 0);
    gather_mean_kernel<<<((size_t)N_PHOTO * 16 + 255) / 256, 256, 0, s_b>>>(
        wh_user, st_p, degi_p, eix_l, out_photo, N_PHOTO);
    cudaEventRecord(evB, s_b);

    // gather_user: needs wh_photo (main) + CSR_likedby (s_c).
    cudaStreamWaitEvent(0, evCSRu, 0);
    gather_mean_kernel<<<((size_t)N_USER * 16 + 255) / 256, 256>>>(
        wh_photo, st_u, degi_u, eix_lb, out_user, N_USER);

    cudaStreamWaitEvent(0, evB, 0);
}

// round 16
// speedup vs baseline: 1.1855x; 1.1855x over previous
#include <cuda_runtime.h>
#include <cuda_fp16.h>
#include <cstdint>

#define N_USER  100000
#define N_PHOTO 200000
#define K_IN    256
#define N_OUT   64
#define E_MAX   1048576

typedef unsigned long long ull;

// Scratch (static device globals; no allocs). Wh tables fp16.
__device__ __half g_Wh_user [(size_t)N_USER  * N_OUT];  // 12.8 MB
__device__ __half g_Wh_photo[(size_t)N_PHOTO * N_OUT];  // 25.6 MB
__device__ ull    g_Bpack_likes  [8192];                // packed tf32 W (64 KB)
__device__ ull    g_Bpack_likedby[8192];
// CSR scratch (per dst ntype)
__device__ int g_degi_user  [N_USER];
__device__ int g_degi_photo [N_PHOTO];
__device__ int g_starts_user [N_USER];
__device__ int g_starts_photo[N_PHOTO];
__device__ int g_cursor_user [N_USER];
__device__ int g_cursor_photo[N_PHOTO];
__device__ int g_eidx_likes  [E_MAX];   // src ids grouped by photo dst
__device__ int g_eidx_likedby[E_MAX];   // src ids grouped by user dst
__device__ int g_bsum_a[256], g_boff_a[256];
__device__ int g_bsum_b[256], g_boff_b[256];

__device__ __forceinline__ unsigned f2tf32(float f) {
    unsigned r;
    asm("cvt.rna.tf32.f32 %0, %1;" : "=r"(r) : "f"(f));
    return r;
}

__device__ __forceinline__ void cp_async16(unsigned dst_smem, const void* src,
                                           unsigned src_bytes) {
    asm volatile("cp.async.cg.shared.global [%0], [%1], 16, %2;"
                 :: "r"(dst_smem), "l"(src), "r"(src_bytes) : "memory");
}

// ---------------------------------------------------------------------------
// Prepack W[256,64] -> fragment-ordered tf32 ull table (see R5 comment).
// ---------------------------------------------------------------------------
__global__ __launch_bounds__(256) void prepack_B(
    const float* __restrict__ W, ull* __restrict__ out)
{
    int i = blockIdx.x * 256 + threadIdx.x;      // 0..8191
    int e = i & 1, u = i >> 1;
    int t = u & 3, g = (u >> 2) & 7, jj = (u >> 5) & 3, kk = u >> 7;
    int n  = (2 * jj + e) * 8 + g;
    int k1 = kk * 8 + t;
    unsigned lo = f2tf32(W[(size_t)k1 * 64 + n]);
    unsigned hi = f2tf32(W[(size_t)(k1 + 4) * 64 + n]);
    out[i] = ((ull)hi << 32) | (ull)lo;
}

// ---------------------------------------------------------------------------
// Tensor-core GEMM (R13 proven config): BM=256, STAGES=2, 2 CTAs/SM.
// ---------------------------------------------------------------------------
#define BM        256
#define STAGES    2
#define ASTRIDE   36
#define AS_STAGE  (BM * ASTRIDE)               // 9216 floats = 36 KB
#define BS_STAGE  1024                         // ulls = 8 KB
#define SMEM_A_BYTES (STAGES * AS_STAGE * 4)   // 73728
#define SMEM_B_BYTES (STAGES * BS_STAGE * 8)   // 16384
#define GEMM_SMEM    (SMEM_A_BYTES + SMEM_B_BYTES)   // 90112

__global__ __launch_bounds__(256, 2) void gemm_tc(
    const float* __restrict__ A, const ull* __restrict__ Bpack,
    const float* __restrict__ bias, __half* __restrict__ C, int M)
{
    extern __shared__ char smem_raw[];
    float* As = (float*)smem_raw;
    ull*   Bs = (ull*)(smem_raw + SMEM_A_BYTES);
    const unsigned sA = (unsigned)__cvta_generic_to_shared(As);
    const unsigned sB = (unsigned)__cvta_generic_to_shared(Bs);

    const int tid  = threadIdx.x;
    const int lane = tid & 31;
    const int warp = tid >> 5;
    const int g = lane >> 2;
    const int t = lane & 3;
    const int rowBase = blockIdx.x * BM;
    const int segA = lane & 7;
    const int rA   = lane >> 3;

    float acc[2][8][4];
#pragma unroll
    for (int m = 0; m < 2; m++)
#pragma unroll
        for (int j = 0; j < 8; j++)
#pragma unroll
            for (int q = 0; q < 4; q++) acc[m][j][q] = 0.f;

#define ISSUE_CHUNK(c, stage)                                                  \
    do {                                                                       \
        _Pragma("unroll")                                                      \
        for (int it = 0; it < 8; it++) {                                       \
            int rin  = warp * 32 + it * 4 + rA;                                \
            int grow = rowBase + rin;                                          \
            const float* srcp = A + (size_t)grow * K_IN + (c) * 32 + segA * 4; \
            unsigned sz  = (grow < M) ? 16u : 0u;                              \
            unsigned dst = sA + ((stage) * AS_STAGE + rin * ASTRIDE            \
                                 + segA * 4) * 4;                              \
            cp_async16(dst, srcp, sz);                                         \
        }                                                                      \
        _Pragma("unroll")                                                      \
        for (int j = 0; j < 2; j++) {                                          \
            int chunk = tid + j * 256;                                         \
            const ull* srcb = Bpack + (size_t)(c) * 1024 + chunk * 2;          \
            unsigned dst = sB + ((stage) * BS_STAGE + chunk * 2) * 8;          \
            cp_async16(dst, srcb, 16u);                                        \
        }                                                                      \
    } while (0)

    // prologue: both stages
    ISSUE_CHUNK(0, 0);
    asm volatile("cp.async.commit_group;" ::: "memory");
    ISSUE_CHUNK(1, 1);
    asm volatile("cp.async.commit_group;" ::: "memory");

    for (int c = 0; c < 8; c++) {
        asm volatile("cp.async.wait_group 1;" ::: "memory");
        __syncthreads();                          // chunk c visible CTA-wide

        const int s = c & 1;
        const float* as = As + s * AS_STAGE + (warp * 32) * ASTRIDE;
        const uint4* bs = (const uint4*)(Bs + s * BS_STAGE);
#pragma unroll
        for (int kl = 0; kl < 4; kl++) {
            uint4 bv[4];
#pragma unroll
            for (int jj = 0; jj < 4; jj++)
                bv[jj] = bs[kl * 128 + jj * 32 + g * 4 + t];   // conflict-free
#pragma unroll
            for (int m = 0; m < 2; m++) {
                const float* am = as + m * 16 * ASTRIDE;
                unsigned a0 = f2tf32(am[(g)     * ASTRIDE + kl * 8 + t]);
                unsigned a1 = f2tf32(am[(g + 8) * ASTRIDE + kl * 8 + t]);
                unsigned a2 = f2tf32(am[(g)     * ASTRIDE + kl * 8 + t + 4]);
                unsigned a3 = f2tf32(am[(g + 8) * ASTRIDE + kl * 8 + t + 4]);
#pragma unroll
                for (int jj = 0; jj < 4; jj++) {
                    asm volatile(
                        "mma.sync.aligned.m16n8k8.row.col.f32.tf32.tf32.f32 "
                        "{%0,%1,%2,%3}, {%4,%5,%6,%7}, {%8,%9}, {%0,%1,%2,%3};"
                        : "+f"(acc[m][2 * jj][0]), "+f"(acc[m][2 * jj][1]),
                          "+f"(acc[m][2 * jj][2]), "+f"(acc[m][2 * jj][3])
                        : "r"(a0), "r"(a1), "r"(a2), "r"(a3),
                          "r"(bv[jj].x), "r"(bv[jj].y));
                    asm volatile(
                        "mma.sync.aligned.m16n8k8.row.col.f32.tf32.tf32.f32 "
                        "{%0,%1,%2,%3}, {%4,%5,%6,%7}, {%8,%9}, {%0,%1,%2,%3};"
                        : "+f"(acc[m][2 * jj + 1][0]), "+f"(acc[m][2 * jj + 1][1]),
                          "+f"(acc[m][2 * jj + 1][2]), "+f"(acc[m][2 * jj + 1][3])
                        : "r"(a0), "r"(a1), "r"(a2), "r"(a3),
                          "r"(bv[jj].z), "r"(bv[jj].w));
                }
            }
        }

        // refill the stage just consumed (all threads past compute of c)
        __syncthreads();
        if (c + 2 < 8) ISSUE_CHUNK(c + 2, s);
        asm volatile("cp.async.commit_group;" ::: "memory");
    }

    // epilogue: bias + fp16 store
#pragma unroll
    for (int m = 0; m < 2; m++) {
        int r0 = rowBase + warp * 32 + m * 16 + g;
#pragma unroll
        for (int j = 0; j < 8; j++) {
            int col = j * 8 + 2 * t;
            float b0 = __ldg(&bias[col]), b1 = __ldg(&bias[col + 1]);
            if (r0 < M)
                *(__half2*)&C[(size_t)r0 * N_OUT + col] =
                    __floats2half2_rn(acc[m][j][0] + b0, acc[m][j][1] + b1);
            if (r0 + 8 < M)
                *(__half2*)&C[(size_t)(r0 + 8) * N_OUT + col] =
                    __floats2half2_rn(acc[m][j][2] + b0, acc[m][j][3] + b1);
        }
    }
#undef ISSUE_CHUNK
}

// ---------------------------------------------------------------------------
// CSR build: int in-degrees -> exclusive prefix scan -> cursor fill.
// ---------------------------------------------------------------------------
__global__ __launch_bounds__(256) void degree_int_kernel(
    const int* __restrict__ dst, int* __restrict__ deg, int E)
{
    int base = (blockIdx.x * 256 + threadIdx.x) * 4;
    if (base + 3 < E) {
        int4 d = *(const int4*)(dst + base);
        atomicAdd(&deg[d.x], 1);
        atomicAdd(&deg[d.y], 1);
        atomicAdd(&deg[d.z], 1);
        atomicAdd(&deg[d.w], 1);
    } else {
        for (int e = base; e < E; e++) atomicAdd(&deg[dst[e]], 1);
    }
}

#define SCAN_BLK 1024   // elements per scan block (256 thr x 4)

__global__ __launch_bounds__(256) void scan_partial(
    const int* __restrict__ deg, int n, int* __restrict__ bsum)
{
    __shared__ int sh[256];
    int b = blockIdx.x, tid = threadIdx.x;
    int base = b * SCAN_BLK;
    int s = 0;
#pragma unroll
    for (int j = 0; j < 4; j++) {
        int idx = base + tid * 4 + j;
        s += (idx < n) ? deg[idx] : 0;
    }
    sh[tid] = s;
    __syncthreads();
    for (int o = 128; o > 0; o >>= 1) {
        if (tid < o) sh[tid] += sh[tid + o];
        __syncthreads();
    }
    if (tid == 0) bsum[b] = sh[0];
}

__global__ __launch_bounds__(256) void scan_bsums(
    const int* __restrict__ bsum, int nb, int* __restrict__ boff)
{
    __shared__ int sh[256];
    int tid = threadIdx.x;
    int v = (tid < nb) ? bsum[tid] : 0;
    sh[tid] = v;
    __syncthreads();
    for (int o = 1; o < 256; o <<= 1) {
        int y = (tid >= o) ? sh[tid - o] : 0;
        __syncthreads();
        sh[tid] += y;
        __syncthreads();
    }
    if (tid < nb) boff[tid] = sh[tid] - v;   // exclusive
}

__global__ __launch_bounds__(256) void scan_final(
    const int* __restrict__ deg, int n, const int* __restrict__ boff,
    int* __restrict__ starts, int* __restrict__ cursor)
{
    __shared__ int sh[256];
    int b = blockIdx.x, tid = threadIdx.x;
    int base = b * SCAN_BLK + tid * 4;
    int v[4];
#pragma unroll
    for (int j = 0; j < 4; j++) v[j] = (base + j < n) ? deg[base + j] : 0;
    int tsum = v[0] + v[1] + v[2] + v[3];
    sh[tid] = tsum;
    __syncthreads();
    for (int o = 1; o < 256; o <<= 1) {
        int y = (tid >= o) ? sh[tid - o] : 0;
        __syncthreads();
        sh[tid] += y;
        __syncthreads();
    }
    int off = boff[b] + sh[tid] - tsum;   // block base + thread-exclusive
    int e = 0;
#pragma unroll
    for (int j = 0; j < 4; j++) {
        if (base + j < n) {
            starts[base + j] = off + e;
            cursor[base + j] = off + e;
        }
        e += v[j];
    }
}

__global__ __launch_bounds__(256) void fill_csr(
    const int* __restrict__ src, const int* __restrict__ dst,
    int* __restrict__ cursor, int* __restrict__ eidx, int E)
{
    int base = (blockIdx.x * 256 + threadIdx.x) * 4;
    if (base + 3 < E) {
        int4 s = *(const int4*)(src + base);
        int4 d = *(const int4*)(dst + base);
        int p0 = atomicAdd(&cursor[d.x], 1); eidx[p0] = s.x;
        int p1 = atomicAdd(&cursor[d.y], 1); eidx[p1] = s.y;
        int p2 = atomicAdd(&cursor[d.z], 1); eidx[p2] = s.z;
        int p3 = atomicAdd(&cursor[d.w], 1); eidx[p3] = s.w;
    } else {
        for (int e = base; e < E; e++) {
            int p = atomicAdd(&cursor[dst[e]], 1);
            eidx[p] = src[e];
        }
    }
}

// ---------------------------------------------------------------------------
// CSR gather-aggregate over fp16 Wh, WIDE-FRONT:
// 16 threads/node, lane loads 8B per edge. Up to U eidx loads issue together
// (1 L2 round-trip), then up to U Wh loads issue together (1 more round-trip),
// out-of-range slots substitute zero bits (fp16 0.0 -> unconditional add).
// Typical node (deg <= U) pays exactly 2 L2 latencies; rare deg > U continues
// in a predicated 4-wide loop. U=8 (photo, Poisson-5) / U=16 (user, Poisson-10).
// ---------------------------------------------------------------------------
__device__ __forceinline__ float4 half4_to_float4(uint2 u) {
    __half2 h0 = *(__half2*)&u.x;
    __half2 h1 = *(__half2*)&u.y;
    float2 f0 = __half22float2(h0);
    float2 f1 = __half22float2(h1);
    return make_float4(f0.x, f0.y, f1.x, f1.y);
}

template <int U>
__global__ __launch_bounds__(256) void gather_mean_kernel(
    const __half* __restrict__ Wh, const int* __restrict__ starts,
    const int* __restrict__ deg, const int* __restrict__ eidx,
    float* __restrict__ out, int n)
{
    int t = blockIdx.x * 256 + threadIdx.x;
    int node = t >> 4;
    if (node >= n) return;
    int lane = t & 15;

    int st = __ldg(&starts[node]);
    int dg = __ldg(&deg[node]);
    int end = st + dg;

    // wide front: all eidx loads independent -> 1 round-trip
    int s[U];
#pragma unroll
    for (int i = 0; i < U; i++)
        s[i] = (st + i < end) ? __ldg(&eidx[st + i]) : -1;

    // all Wh loads depend only on their own eidx -> 1 more round-trip
    uint2 u[U];
#pragma unroll
    for (int i = 0; i < U; i++)
        u[i] = (s[i] >= 0)
             ? __ldg(((const uint2*)(Wh + (size_t)s[i] * N_OUT)) + lane)
             : make_uint2(0u, 0u);          // fp16 zero bits

    float4 a0 = make_float4(0.f, 0.f, 0.f, 0.f), a1 = a0;
#pragma unroll
    for (int i = 0; i < U; i += 2) {
        float4 v0 = half4_to_float4(u[i]);
        float4 v1 = half4_to_float4(u[i + 1]);
        a0.x += v0.x; a0.y += v0.y; a0.z += v0.z; a0.w += v0.w;
        a1.x += v1.x; a1.y += v1.y; a1.z += v1.z; a1.w += v1.w;
    }

    // rare overflow (deg > U): predicated 4-wide batches
    for (int k = st + U; k < end; k += 4) {
        int ss[4];
        uint2 uu[4];
#pragma unroll
        for (int i = 0; i < 4; i++)
            ss[i] = (k + i < end) ? __ldg(&eidx[k + i]) : -1;
#pragma unroll
        for (int i = 0; i < 4; i++)
            uu[i] = (ss[i] >= 0)
                  ? __ldg(((const uint2*)(Wh + (size_t)ss[i] * N_OUT)) + lane)
                  : make_uint2(0u, 0u);
#pragma unroll
        for (int i = 0; i < 4; i += 2) {
            float4 v0 = half4_to_float4(uu[i]);
            float4 v1 = half4_to_float4(uu[i + 1]);
            a0.x += v0.x; a0.y += v0.y; a0.z += v0.z; a0.w += v0.w;
            a1.x += v1.x; a1.y += v1.y; a1.z += v1.z; a1.w += v1.w;
        }
    }

    float inv = 1.0f / (float)max(dg, 1);
    float4 acc = make_float4((a0.x + a1.x) * inv, (a0.y + a1.y) * inv,
                             (a0.z + a1.z) * inv, (a0.w + a1.w) * inv);
    ((float4*)(out + (size_t)node * N_OUT))[lane] = acc;
}

// ---------------------------------------------------------------------------
extern "C" void kernel_launch(void* const* d_in, const int* in_sizes, int n_in,
                              void* d_out, int out_size)
{
    const float* user_feats  = (const float*)d_in[0];
    const float* photo_feats = (const float*)d_in[1];
    const float* W_likes     = (const float*)d_in[2];
    const float* b_likes     = (const float*)d_in[3];
    const float* W_likedby   = (const float*)d_in[4];
    const float* b_likedby   = (const float*)d_in[5];
    const int*   likes_src   = (const int*)d_in[6];
    const int*   likes_dst   = (const int*)d_in[7];
    const int*   likedby_src = (const int*)d_in[8];
    const int*   likedby_dst = (const int*)d_in[9];
    const int E1 = in_sizes[6];
    const int E2 = in_sizes[8];

    float* out_user  = (float*)d_out;
    float* out_photo = (float*)d_out + (size_t)N_USER * N_OUT;

    __half *wh_user, *wh_photo;
    ull *bp_likes, *bp_likedby;
    int *degi_u, *degi_p, *st_u, *st_p, *cur_u, *cur_p, *eix_l, *eix_lb;
    int *bsum_a, *boff_a, *bsum_b, *boff_b;
    cudaGetSymbolAddress((void**)&wh_user,  g_Wh_user);
    cudaGetSymbolAddress((void**)&wh_photo, g_Wh_photo);
    cudaGetSymbolAddress((void**)&bp_likes,   g_Bpack_likes);
    cudaGetSymbolAddress((void**)&bp_likedby, g_Bpack_likedby);
    cudaGetSymbolAddress((void**)&degi_u, g_degi_user);
    cudaGetSymbolAddress((void**)&degi_p, g_degi_photo);
    cudaGetSymbolAddress((void**)&st_u,   g_starts_user);
    cudaGetSymbolAddress((void**)&st_p,   g_starts_photo);
    cudaGetSymbolAddress((void**)&cur_u,  g_cursor_user);
    cudaGetSymbolAddress((void**)&cur_p,  g_cursor_photo);
    cudaGetSymbolAddress((void**)&eix_l,  g_eidx_likes);
    cudaGetSymbolAddress((void**)&eix_lb, g_eidx_likedby);
    cudaGetSymbolAddress((void**)&bsum_a, g_bsum_a);
    cudaGetSymbolAddress((void**)&boff_a, g_boff_a);
    cudaGetSymbolAddress((void**)&bsum_b, g_bsum_b);
    cudaGetSymbolAddress((void**)&boff_b, g_boff_b);

    static cudaStream_t s_b = nullptr, s_aux = nullptr, s_c = nullptr;
    static cudaEvent_t evStart, evCSRp, evCSRu, evB;
    if (!s_b) {
        int loPri, hiPri;
        cudaDeviceGetStreamPriorityRange(&loPri, &hiPri);
        cudaStreamCreateWithPriority(&s_b,   cudaStreamNonBlocking, hiPri);
        cudaStreamCreateWithPriority(&s_aux, cudaStreamNonBlocking, loPri);
        cudaStreamCreateWithPriority(&s_c,   cudaStreamNonBlocking, loPri);
        cudaEventCreateWithFlags(&evStart, cudaEventDisableTiming);
        cudaEventCreateWithFlags(&evCSRp,  cudaEventDisableTiming);
        cudaEventCreateWithFlags(&evCSRu,  cudaEventDisableTiming);
        cudaEventCreateWithFlags(&evB,     cudaEventDisableTiming);
        cudaFuncSetAttribute(gemm_tc,
                             cudaFuncAttributeMaxDynamicSharedMemorySize,
                             GEMM_SMEM);
    }

    const int nbP = (N_PHOTO + SCAN_BLK - 1) / SCAN_BLK;   // 196
    const int nbU = (N_USER  + SCAN_BLK - 1) / SCAN_BLK;   // 98

    cudaEventRecord(evStart, 0);
    cudaStreamWaitEvent(s_b,   evStart, 0);
    cudaStreamWaitEvent(s_aux, evStart, 0);
    cudaStreamWaitEvent(s_c,   evStart, 0);

    // ---- Critical chain first: GEMMs claim the chip before CSR work. ----
    // MAIN: prepack(likedby) -> gemm_photo (the LONG gemm) -> gather_user.
    // s_b:  prepack(likes)   -> gemm_user  (the short gemm) -> gather_photo.
    prepack_B<<<32, 256>>>(W_likedby, bp_likedby);
    prepack_B<<<32, 256, 0, s_b>>>(W_likes, bp_likes);

    gemm_tc<<<(N_PHOTO + BM - 1) / BM, 256, GEMM_SMEM>>>(
        photo_feats, bp_likedby, b_likedby, wh_photo, N_PHOTO);
    gemm_tc<<<(N_USER + BM - 1) / BM, 256, GEMM_SMEM, s_b>>>(
        user_feats,  bp_likes,   b_likes,   wh_user,  N_USER);

    // ---- CSR builds (backfill the chip during the GEMM phase). ----
    // s_aux: CSR for 'likes' (grouped by photo dst).
    cudaMemsetAsync(degi_p, 0, N_PHOTO * sizeof(int), s_aux);
    degree_int_kernel<<<(E1 + 1023) / 1024, 256, 0, s_aux>>>(likes_dst, degi_p, E1);
    scan_partial<<<nbP, 256, 0, s_aux>>>(degi_p, N_PHOTO, bsum_a);
    scan_bsums<<<1, 256, 0, s_aux>>>(bsum_a, nbP, boff_a);
    scan_final<<<nbP, 256, 0, s_aux>>>(degi_p, N_PHOTO, boff_a, st_p, cur_p);
    fill_csr<<<(E1 + 1023) / 1024, 256, 0, s_aux>>>(likes_src, likes_dst, cur_p, eix_l, E1);
    cudaEventRecord(evCSRp, s_aux);

    // s_c: CSR for 'likedby' (grouped by user dst).
    cudaMemsetAsync(degi_u, 0, N_USER * sizeof(int), s_c);
    degree_int_kernel<<<(E2 + 1023) / 1024, 256, 0, s_c>>>(likedby_dst, degi_u, E2);
    scan_partial<<<nbU, 256, 0, s_c>>>(degi_u, N_USER, bsum_b);
    scan_bsums<<<1, 256, 0, s_c>>>(bsum_b, nbU, boff_b);
    scan_final<<<nbU, 256, 0, s_c>>>(degi_u, N_USER, boff_b, st_u, cur_u);
    fill_csr<<<(E2 + 1023) / 1024, 256, 0, s_c>>>(likedby_src, likedby_dst, cur_u, eix_lb, E2);
    cudaEventRecord(evCSRu, s_c);

    // ---- Gathers. ----
    // gather_photo (Poisson-5 degrees -> U=8): needs wh_user (s_b) + CSR_likes.
    cudaStreamWaitEvent(s_b, evCSRp, 0);
    gather_mean_kernel<8><<<((size_t)N_PHOTO * 16 + 255) / 256, 256, 0, s_b>>>(
        wh_user, st_p, degi_p, eix_l, out_photo, N_PHOTO);
    cudaEventRecord(evB, s_b);

    // gather_user (Poisson-10 degrees -> U=16): needs wh_photo + CSR_likedby.
    cudaStreamWaitEvent(0, evCSRu, 0);
    gather_mean_kernel<16><<<((size_t)N_USER * 16 + 255) / 256, 256>>>(
        wh_photo, st_u, degi_u, eix_lb, out_user, N_USER);

    cudaStreamWaitEvent(0, evB, 0);
}